// round 1
// baseline (speedup 1.0000x reference)
#include <cuda_runtime.h>

// Problem constants
#define NROWS   512      // 16 * 32
#define HORIZON 32
#define NP      256      // particles per row (2560 / 10)
#define OD      10       // OBS_DIM
#define AD      4        // ACTION_DIM
#define ROW_LEN 2564

__device__ float g_chamfer[NROWS];
__device__ float g_action[NROWS];
__device__ float g_a0[NROWS];

__global__ __launch_bounds__(256, 4)
void chamfer_row_kernel(const float* __restrict__ preds,
                        const float* __restrict__ targ) {
    const int r = blockIdx.x;          // row = b*32 + h
    const int t = threadIdx.x;         // particle index (0..255)
    const float* __restrict__ pr = preds + (size_t)r * ROW_LEN;
    const float* __restrict__ tg = targ  + (size_t)r * ROW_LEN;

    __shared__ float  obs_s[NP * OD];   // 10 KB
    __shared__ float  obt_s[NP * OD];   // 10 KB
    __shared__ float4 fA[NP];           // feat of obs  (dims 5..8)  4 KB
    __shared__ float4 fB[NP];           // feat of targ (dims 5..8)  4 KB
    __shared__ float  red[256];

    // stage full obs rows
    #pragma unroll
    for (int i = t; i < NP * OD; i += 256) {
        obs_s[i] = pr[AD + i];
        obt_s[i] = tg[AD + i];
    }
    __syncthreads();

    // compact feature vectors (one per particle)
    fA[t] = make_float4(obs_s[t*OD+5], obs_s[t*OD+6], obs_s[t*OD+7], obs_s[t*OD+8]);
    fB[t] = make_float4(obt_s[t*OD+5], obt_s[t*OD+6], obt_s[t*OD+7], obt_s[t*OD+8]);
    __syncthreads();

    // per-thread registers: this thread's own features
    const float4 myA = fA[t];   // used when t acts as row index i (scan over j)
    const float4 myB = fB[t];   // used when t acts as col index j (scan over i)

    // Single fused scan: k plays both roles.
    //   idx1[t] = argmin_i  P[i][t]   (compare fA[k] against myB)
    //   idx2[t] = argmin_j  P[t][j]   (compare myA against fB[k])
    float best1 = 3.402823466e38f, best2 = 3.402823466e38f;
    int i1 = 0, i2 = 0;
    #pragma unroll 4
    for (int k = 0; k < NP; ++k) {
        float4 a = fA[k];                       // broadcast LDS.128
        float d0 = a.x - myB.x, d1 = a.y - myB.y;
        float d2 = a.z - myB.z, d3 = a.w - myB.w;
        float p = d0*d0 + d1*d1 + d2*d2 + d3*d3;
        if (p < best1) { best1 = p; i1 = k; }   // first-min tie-break (strict <, ascending k)

        float4 b = fB[k];                       // broadcast LDS.128
        float e0 = myA.x - b.x, e1 = myA.y - b.y;
        float e2 = myA.z - b.z, e3 = myA.w - b.w;
        float q = e0*e0 + e1*e1 + e2*e2 + e3*e3;
        if (q < best2) { best2 = q; i2 = k; }
    }

    // particle_dist1[t,:] = |obs[i1] - obs_targ[t]|
    // particle_dist2[t,:] = |obs_targ[i2] - obs[t]|
    float s1 = 0.f, s2 = 0.f;
    #pragma unroll
    for (int d = 0; d < OD; ++d) {
        s1 += fabsf(obs_s[i1 * OD + d] - obt_s[t * OD + d]);
        s2 += fabsf(obt_s[i2 * OD + d] - obs_s[t * OD + d]);
    }
    float contrib = (3.0f * s1 + s2) * 0.25f;   // (TARGET_WEIGHT*d1 + d2)/(TARGET_WEIGHT+1)

    // deterministic block tree-reduce of the 256 per-particle sums
    red[t] = contrib;
    __syncthreads();
    #pragma unroll
    for (int off = 128; off > 0; off >>= 1) {
        if (t < off) red[t] += red[t + off];
        __syncthreads();
    }

    if (t == 0) {
        g_chamfer[r] = red[0];
        // action L1 for this (b,h): mean over 4 dims
        float al1 = 0.f;
        #pragma unroll
        for (int d = 0; d < AD; ++d) al1 += fabsf(pr[d] - tg[d]);
        al1 *= 0.25f;
        int h = r & (HORIZON - 1);
        g_action[r] = (h == 1) ? al1 * 10.0f : al1;  // A0_WEIGHT on h==1
        g_a0[r]     = (h == 1) ? al1 : 0.0f;
    }
}

__global__ __launch_bounds__(512)
void final_reduce_kernel(float* __restrict__ out) {
    __shared__ float s1[NROWS], s2[NROWS], s3[NROWS];
    const int t = threadIdx.x;
    s1[t] = g_chamfer[t];
    s2[t] = g_action[t];
    s3[t] = g_a0[t];
    __syncthreads();
    #pragma unroll
    for (int off = 256; off > 0; off >>= 1) {
        if (t < off) {
            s1[t] += s1[t + off];
            s2[t] += s2[t + off];
            s3[t] += s3[t + off];
        }
        __syncthreads();
    }
    if (t == 0) {
        float chamfer_mean = s1[0] / ((float)NROWS * NP * OD);  // / 1,310,720
        float action_loss  = s2[0] / (float)NROWS;              // / 512
        float a0_loss      = s3[0] / 16.0f;                     // mean over batch
        out[0] = action_loss + chamfer_mean;
        out[1] = a0_loss;
    }
}

extern "C" void kernel_launch(void* const* d_in, const int* in_sizes, int n_in,
                              void* d_out, int out_size) {
    const float* preds = (const float*)d_in[0];
    const float* targ  = (const float*)d_in[1];
    float* out = (float*)d_out;
    chamfer_row_kernel<<<NROWS, 256>>>(preds, targ);
    final_reduce_kernel<<<1, NROWS>>>(out);
}

// round 3
// speedup vs baseline: 1.1707x; 1.1707x over previous
#include <cuda_runtime.h>

#define NROWS   512      // 16 * 32
#define NP      256      // particles per row
#define OD      10       // OBS_DIM
#define AD      4        // ACTION_DIM
#define ROW_LEN 2564
#define NBLK    1024     // (row, dir) blocks

__device__ float g_partial[NBLK];
__device__ float g_action[NROWS];
__device__ float g_a0[NROWS];
__device__ int   g_cnt;          // zero-init; last block resets it each run

typedef unsigned long long ull;

__device__ __forceinline__ ull pk2(float a, float b) {
    ull r; asm("mov.b64 %0, {%1, %2};" : "=l"(r) : "f"(a), "f"(b)); return r;
}
__device__ __forceinline__ ull add2_(ull a, ull b) {
    ull r; asm("add.rn.f32x2 %0, %1, %2;" : "=l"(r) : "l"(a), "l"(b)); return r;
}
__device__ __forceinline__ ull fma2_(ull a, ull b, ull c) {
    ull r; asm("fma.rn.f32x2 %0, %1, %2, %3;" : "=l"(r) : "l"(a), "l"(b), "l"(c)); return r;
}
__device__ __forceinline__ unsigned umin_(unsigned a, unsigned b) { return a < b ? a : b; }

__global__ __launch_bounds__(128, 8)
void chamfer_kernel(const float* __restrict__ preds,
                    const float* __restrict__ targ,
                    float* __restrict__ out) {
    const int blk = blockIdx.x;
    const int r   = blk >> 1;        // row = b*32 + h
    const int dir = blk & 1;         // 0: argmin over obs (idx1), 1: argmin over targ (idx2)
    const int t   = threadIdx.x;

    __shared__ float obs_s[NP * OD];        // 10 KB
    __shared__ float obt_s[NP * OD];        // 10 KB
    __shared__ ulonglong2 sxy[NP / 2];      // packed (x-pair, y-pair)  2 KB
    __shared__ ulonglong2 szw[NP / 2];      // packed (z-pair, w-pair)  2 KB
    __shared__ ull        shn[NP / 2];      // packed half-norm pairs   1 KB
    __shared__ float red[128];
    __shared__ int s_last;

    // ---- stage obs rows (float4, base is 16B-aligned: (r*2564+4)*4 % 16 == 0) ----
    const float4* pr4 = (const float4*)(preds + (size_t)r * ROW_LEN + AD);
    const float4* tg4 = (const float4*)(targ  + (size_t)r * ROW_LEN + AD);
    #pragma unroll
    for (int i = t; i < NP * OD / 4; i += 128) {
        ((float4*)obs_s)[i] = pr4[i];
        ((float4*)obt_s)[i] = tg4[i];
    }
    __syncthreads();

    const float* scan = dir ? obt_s : obs_s;   // side we argmin over
    const float* mine = dir ? obs_s : obt_s;   // side providing the query columns

    // ---- pack scan-side features (dims 5..8) as f32x2 pairs + half-norms ----
    {
        const int k0 = 2 * t, k1 = 2 * t + 1;
        float x0 = scan[k0*OD+5], y0 = scan[k0*OD+6], z0 = scan[k0*OD+7], w0 = scan[k0*OD+8];
        float x1 = scan[k1*OD+5], y1 = scan[k1*OD+6], z1 = scan[k1*OD+7], w1 = scan[k1*OD+8];
        sxy[t] = make_ulonglong2(pk2(x0, x1), pk2(y0, y1));
        szw[t] = make_ulonglong2(pk2(z0, z1), pk2(w0, w1));
        shn[t] = pk2(0.5f * (x0*x0 + y0*y0 + z0*z0 + w0*w0),
                     0.5f * (x1*x1 + y1*y1 + z1*z1 + w1*w1));
    }
    __syncthreads();

    // ---- per-thread query columns: cA = t, cB = t + 128 ----
    const int cA = t, cB = t + 128;
    const float ax = mine[cA*OD+5], ay = mine[cA*OD+6], az = mine[cA*OD+7], aw = mine[cA*OD+8];
    const float bx = mine[cB*OD+5], by = mine[cB*OD+6], bz = mine[cB*OD+7], bw = mine[cB*OD+8];
    const ull nAx = pk2(-ax, -ax), nAy = pk2(-ay, -ay), nAz = pk2(-az, -az), nAw = pk2(-aw, -aw);
    const ull nBx = pk2(-bx, -bx), nBy = pk2(-by, -by), nBz = pk2(-bz, -bz), nBw = pk2(-bw, -bw);
    const float hA = 1.0f + 0.5f * (ax*ax + ay*ay + az*az + aw*aw);
    const float hB = 1.0f + 0.5f * (bx*bx + by*by + bz*bz + bw*bw);
    const ull baseA = pk2(hA, hA);
    const ull baseB = pk2(hB, hB);

    // score = 1 + half|a|^2 + half|b|^2 - a.b  (monotone in squared distance, >= ~1: sign bit 0)
    // key = (score_bits & ~0xFF) | k  -> unsigned min gives first-occurrence argmin
    unsigned bestA = 0xFFFFFFFFu, bestB = 0xFFFFFFFFu;
    #pragma unroll 4
    for (int kk = 0; kk < NP / 2; ++kk) {
        const ulonglong2 xy = sxy[kk];
        const ulonglong2 zw = szw[kk];
        const ull h2 = shn[kk];

        ull sA = add2_(h2, baseA);
        sA = fma2_(xy.x, nAx, sA);
        sA = fma2_(xy.y, nAy, sA);
        sA = fma2_(zw.x, nAz, sA);
        sA = fma2_(zw.y, nAw, sA);

        ull sB = add2_(h2, baseB);
        sB = fma2_(xy.x, nBx, sB);
        sB = fma2_(xy.y, nBy, sB);
        sB = fma2_(zw.x, nBz, sB);
        sB = fma2_(zw.y, nBw, sB);

        const unsigned k0 = 2u * kk, k1 = 2u * kk + 1u;
        bestA = umin_(bestA, ((unsigned)sA         & 0xFFFFFF00u) | k0);
        bestA = umin_(bestA, ((unsigned)(sA >> 32) & 0xFFFFFF00u) | k1);
        bestB = umin_(bestB, ((unsigned)sB         & 0xFFFFFF00u) | k0);
        bestB = umin_(bestB, ((unsigned)(sB >> 32) & 0xFFFFFF00u) | k1);
    }

    const int iA = bestA & 0xFF;
    const int iB = bestB & 0xFF;

    // ---- L1 gather over all 10 dims ----
    float s1 = 0.f, s2 = 0.f;
    #pragma unroll
    for (int d = 0; d < OD; ++d) {
        s1 += fabsf(scan[iA * OD + d] - mine[cA * OD + d]);
        s2 += fabsf(scan[iB * OD + d] - mine[cB * OD + d]);
    }
    const float w = dir ? 1.0f : 3.0f;   // TARGET_WEIGHT on the idx1 path
    red[t] = w * (s1 + s2);
    __syncthreads();
    #pragma unroll
    for (int off = 64; off > 0; off >>= 1) {
        if (t < off) red[t] += red[t + off];
        __syncthreads();
    }

    if (t == 0) {
        g_partial[blk] = red[0];
        if (dir == 0) {
            const float* pr = preds + (size_t)r * ROW_LEN;
            const float* tg = targ  + (size_t)r * ROW_LEN;
            float al1 = 0.f;
            #pragma unroll
            for (int d = 0; d < AD; ++d) al1 += fabsf(pr[d] - tg[d]);
            al1 *= 0.25f;
            const int h = r & 31;
            g_action[r] = (h == 1) ? al1 * 10.0f : al1;
            g_a0[r]     = (h == 1) ? al1 : 0.0f;
        }
        __threadfence();
        const int ticket = atomicAdd(&g_cnt, 1);
        s_last = (ticket == NBLK - 1) ? 1 : 0;
    }
    __syncthreads();

    // ---- fused final reduction: last block to finish does it ----
    if (s_last) {
        float c = 0.f;
        for (int i = t; i < NBLK; i += 128) c += g_partial[i];
        red[t] = c;
        __syncthreads();
        #pragma unroll
        for (int off = 64; off > 0; off >>= 1) {
            if (t < off) red[t] += red[t + off];
            __syncthreads();
        }
        const float chamfer_total = red[0];
        __syncthreads();

        float a = 0.f;
        for (int i = t; i < NROWS; i += 128) a += g_action[i];
        red[t] = a;
        __syncthreads();
        #pragma unroll
        for (int off = 64; off > 0; off >>= 1) {
            if (t < off) red[t] += red[t + off];
            __syncthreads();
        }
        const float action_total = red[0];
        __syncthreads();

        float z = 0.f;
        for (int i = t; i < NROWS; i += 128) z += g_a0[i];
        red[t] = z;
        __syncthreads();
        #pragma unroll
        for (int off = 64; off > 0; off >>= 1) {
            if (t < off) red[t] += red[t + off];
            __syncthreads();
        }
        const float a0_total = red[0];

        if (t == 0) {
            // chamfer mean = total / (4 * 512*256*10)
            out[0] = action_total * (1.0f / NROWS) + chamfer_total * (1.0f / 5242880.0f);
            out[1] = a0_total * (1.0f / 16.0f);
            g_cnt  = 0;   // reset for next graph replay
        }
    }
}

extern "C" void kernel_launch(void* const* d_in, const int* in_sizes, int n_in,
                              void* d_out, int out_size) {
    const float* preds = (const float*)d_in[0];
    const float* targ  = (const float*)d_in[1];
    chamfer_kernel<<<NBLK, 128>>>(preds, targ, (float*)d_out);
}